// round 8
// baseline (speedup 1.0000x reference)
#include <cuda_runtime.h>
#include <cuda_bf16.h>

// Problem constants
#define NBATCH 8
#define CIN    8
#define COUT   16
#define HW     65536        // 256*256
#define NPAR   (COUT * CIN) // 128

typedef unsigned long long ull;

// Packed f32x2 FMA (Blackwell): one instruction, two fp32 lanes.
__device__ __forceinline__ ull ffma2(ull a, ull b, ull c) {
    ull d;
    asm("fma.rn.f32x2 %0, %1, %2, %3;" : "=l"(d) : "l"(a), "l"(b), "l"(c));
    return d;
}

__device__ __forceinline__ float ex2f(float v) {
    float r;
    asm("ex2.approx.f32 %0, %1;" : "=f"(r) : "f"(v));
    return r;
}

// Split a packed f32x2 into its two scalar halves (register aliasing; usually free).
__device__ __forceinline__ void unpack2(ull v, float& lo, float& hi) {
    asm("mov.b64 {%0, %1}, %2;" : "=f"(lo), "=f"(hi) : "l"(v));
}

// Per-(o,j): exp(-(x-c)^2/(2w^2)) = ex2( A*x^2 + B*x + D ), Horner: ((A*x+B)*x+D)
//   A = a, B = -2ac, D = a c^2,  a = -log2(e)/(2w^2)
struct __align__(16) Par { ull pA, pB, pD, pad; };  // each value duplicated into both f32 halves

__global__ __launch_bounds__(256) void soft_hist_kernel(
    const float* __restrict__ x,        // [B][CIN][HW]
    const float* __restrict__ centers,  // [COUT][CIN]
    const float* __restrict__ widths,   // [COUT][CIN]
    float*       __restrict__ out)      // [B][COUT][HW]
{
    __shared__ Par sp[NPAR];
    int t = threadIdx.x;
    if (t < NPAR) {
        float c = centers[t];
        float w = widths[t];
        float A  = -0.72134752044448170f / (w * w);  // -log2(e)/2 / w^2
        float Bv = -2.0f * A * c;
        float D  = A * c * c;
        float2 aa = make_float2(A, A);
        float2 bb = make_float2(Bv, Bv);
        float2 dd = make_float2(D, D);
        sp[t].pA = *(ull*)&aa;
        sp[t].pB = *(ull*)&bb;
        sp[t].pD = *(ull*)&dd;
    }
    __syncthreads();

    // Each thread handles 4 consecutive spatial positions (one float4 / ulonglong2).
    int gv  = blockIdx.x * 256 + t;            // group index in [0, B*HW/4)
    int b   = gv >> 14;                        // HW/4 = 16384 groups per image
    int pos = (gv << 2) & (HW - 1);            // element offset within the image

    // Load 8 input channels x 4 positions as packed pairs (LDG.128 each).
    const float* xin = x + (size_t)b * CIN * HW + pos;
    ull xv[CIN][2];
    #pragma unroll
    for (int j = 0; j < CIN; j++) {
        ulonglong2 v = *(const ulonglong2*)(xin + (size_t)j * HW);
        xv[j][0] = v.x;
        xv[j][1] = v.y;
    }

    float* op = out + (size_t)b * COUT * HW + pos;

    #pragma unroll
    for (int o = 0; o < COUT; o++) {
        float s0 = 0.0f, s1 = 0.0f, s2 = 0.0f, s3 = 0.0f;
        #pragma unroll
        for (int j = 0; j < CIN; j++) {
            const Par* p = &sp[o * CIN + j];
            ulonglong2 ab = *(const ulonglong2*)p;   // LDS.128 -> {pA, pB}
            ull dd = p->pD;                          // LDS.64
            // Horner: ((A*x + B)*x + D), packed over 2 positions each
            ull q0 = ffma2(ffma2(ab.x, xv[j][0], ab.y), xv[j][0], dd);
            ull q1 = ffma2(ffma2(ab.x, xv[j][1], ab.y), xv[j][1], dd);
            float a0, a1, a2, a3;
            unpack2(q0, a0, a1);
            unpack2(q1, a2, a3);
            s0 += ex2f(a0);
            s1 += ex2f(a1);
            s2 += ex2f(a2);
            s3 += ex2f(a3);
        }
        *(float4*)(op + (size_t)o * HW) = make_float4(s0, s1, s2, s3);
    }
}

extern "C" void kernel_launch(void* const* d_in, const int* in_sizes, int n_in,
                              void* d_out, int out_size) {
    const float* x       = (const float*)d_in[0];   // [8,8,256,256]
    const float* centers = (const float*)d_in[1];   // [16,8]
    const float* widths  = (const float*)d_in[2];   // [16,8]
    float* out = (float*)d_out;                     // [8,16,256,256]

    const int groups = NBATCH * HW / 4;             // 131072
    const int block  = 256;
    const int grid   = groups / block;              // 512
    soft_hist_kernel<<<grid, block>>>(x, centers, widths, out);
}